// round 14
// baseline (speedup 1.0000x reference)
#include <cuda_runtime.h>
#include <math.h>
#include <stdint.h>

// ---------------------------------------------------------------------------
// Problem constants
// ---------------------------------------------------------------------------
#define NSAMP  8192
#define NDIMT  3072
#define NKER   64
#define NSUB   48
#define MKNOT  200
#define NTRT   3072

// ---------------------------------------------------------------------------
// Device scratch (static only)
// ---------------------------------------------------------------------------
__device__ float  g_Q  [NKER * NSUB * NSUB];   // [k][j][i]
__device__ float  g_QT [NKER * NSUB * NSUB];   // [k][i][j]
__device__ float  g_xx [NTRT * MKNOT];         // x knots
__device__ float2 g_yd [NTRT * MKNOT];         // (y, d) knots, interleaved
__device__ float  g_lj [NKER * NSAMP];
__device__ unsigned char g_lut[NTRT * 256];
__device__ float  g_lxlo[NTRT];
__device__ float  g_livw[NTRT];

// ---------------------------------------------------------------------------
// f32x2 helpers (packed fp32 — exact fp32 per lane)
// ---------------------------------------------------------------------------
__device__ __forceinline__ void ffma2(unsigned long long& acc,
                                      unsigned long long a, unsigned long long b) {
    asm("fma.rn.f32x2 %0, %1, %2, %0;" : "+l"(acc) : "l"(a), "l"(b));
}
__device__ __forceinline__ unsigned long long splat2(float v) {
    unsigned long long r;
    asm("mov.b64 %0, {%1, %1};" : "=l"(r) : "f"(v));
    return r;
}
__device__ __forceinline__ float2 unpk2(unsigned long long v) {
    float2 r;
    asm("mov.b64 {%0, %1}, %2;" : "=f"(r.x), "=f"(r.y) : "l"(v));
    return r;
}
#define HALF_BAR(h) asm volatile("bar.sync %0, %1;" :: "r"((h) + 1), "r"(384) : "memory")

// ---------------------------------------------------------------------------
// Kernel 1: per-patch MGS QR (positive diagonal), writes Q and Q^T.
// ---------------------------------------------------------------------------
__global__ void orth_kernel(const float* __restrict__ A_raw) {
    const int k   = blockIdx.x;
    const int tid = threadIdx.x;
    __shared__ float qcol[NSUB];

    float col[NSUB];
    const float* Ab = A_raw + k * (NSUB * NSUB);
    if (tid < NSUB) {
#pragma unroll
        for (int r = 0; r < NSUB; ++r) col[r] = Ab[r * NSUB + tid];
    }

    for (int c = 0; c < NSUB; ++c) {
        if (tid == c) {
            float nrm = 0.f;
#pragma unroll
            for (int r = 0; r < NSUB; ++r) nrm += col[r] * col[r];
            float inv = 1.0f / sqrtf(nrm);
#pragma unroll
            for (int r = 0; r < NSUB; ++r) { col[r] *= inv; qcol[r] = col[r]; }
        }
        __syncthreads();
        if (tid < NSUB) {
            if (tid == c) {
                float* gq  = g_Q  + k * (NSUB * NSUB);
                float* gqt = g_QT + k * (NSUB * NSUB);
#pragma unroll
                for (int r = 0; r < NSUB; ++r) {
                    gq [r * NSUB + c] = qcol[r];
                    gqt[c * NSUB + r] = qcol[r];
                }
            } else if (tid > c) {
                float dot = 0.f;
#pragma unroll
                for (int r = 0; r < NSUB; ++r) dot += qcol[r] * col[r];
#pragma unroll
                for (int r = 0; r < NSUB; ++r) col[r] -= dot * qcol[r];
            }
        }
        __syncthreads();
    }
}

// ---------------------------------------------------------------------------
// Kernel 2: knot tables via warp scans. y/d written interleaved into g_yd.
// ---------------------------------------------------------------------------
__global__ void knots_kernel(const float* __restrict__ x0,
                             const float* __restrict__ logdx,
                             const float* __restrict__ y0,
                             const float* __restrict__ logdy,
                             const float* __restrict__ logderiv) {
    const int warp = (blockIdx.x * blockDim.x + threadIdx.x) >> 5;
    const int lane = threadIdx.x & 31;
    if (warp >= NTRT) return;

    {
        float carry = x0[warp];
        if (lane == 0) g_xx[warp * MKNOT] = carry;
        const float* src = logdx + (size_t)warp * (MKNOT - 1);
        for (int c = 0; c < MKNOT - 1; c += 32) {
            int m = c + lane;
            float v = (m < MKNOT - 1) ? expf(src[m]) : 0.f;
#pragma unroll
            for (int off = 1; off < 32; off <<= 1) {
                float o = __shfl_up_sync(0xffffffffu, v, off);
                if (lane >= off) v += o;
            }
            if (m < MKNOT - 1) g_xx[warp * MKNOT + m + 1] = carry + v;
            carry += __shfl_sync(0xffffffffu, v, 31);
        }
    }
    {
        float carry = y0[warp];
        if (lane == 0) g_yd[warp * MKNOT].x = carry;
        const float* src = logdy + (size_t)warp * (MKNOT - 1);
        for (int c = 0; c < MKNOT - 1; c += 32) {
            int m = c + lane;
            float v = (m < MKNOT - 1) ? expf(src[m]) : 0.f;
#pragma unroll
            for (int off = 1; off < 32; off <<= 1) {
                float o = __shfl_up_sync(0xffffffffu, v, off);
                if (lane >= off) v += o;
            }
            if (m < MKNOT - 1) g_yd[warp * MKNOT + m + 1].x = carry + v;
            carry += __shfl_sync(0xffffffffu, v, 31);
        }
    }
    for (int m = lane; m < MKNOT; m += 32)
        g_yd[warp * MKNOT + m].y = expf(logderiv[(size_t)warp * MKNOT + m]);
}

// ---------------------------------------------------------------------------
// Kernel 2b: per-coordinate 256-bin search LUT.
// ---------------------------------------------------------------------------
__global__ void lut_kernel() {
    const int warp = (blockIdx.x * blockDim.x + threadIdx.x) >> 5;
    const int lane = threadIdx.x & 31;
    if (warp >= NTRT) return;
    const float* xr = g_xx + (size_t)warp * MKNOT;
    float xlo = xr[0], xhi = xr[MKNOT - 1];
    float binw = (xhi - xlo) * (1.0f / 256.0f);
    if (lane == 0) { g_lxlo[warp] = xlo; g_livw[warp] = 256.0f / (xhi - xlo); }
#pragma unroll
    for (int t = 0; t < 8; ++t) {
        int q = lane + 32 * t;
        float L = xlo + q * binw;
        int lo = 0, hi = MKNOT;
        while (lo < hi) { int mid = (lo + hi) >> 1; if (xr[mid] < L) lo = mid + 1; else hi = mid; }
        g_lut[(size_t)warp * 256 + q] = (unsigned char)lo;
    }
}

// ---------------------------------------------------------------------------
// Kernel 3: fused pipeline. 768 threads = 2 free-running halves of 384,
// each with private V/S buffers; shared read-only Q/knots/LUT. Named barriers.
// ---------------------------------------------------------------------------
#define TPB      768
#define HTPB     384
#define ROWS_IT  128                    // per half per iter
#define ITERS    2                      // per half
#define RST      132                    // padded row stride (132 % 4 == 0)
#define GELEM    (NSUB * ROWS_IT)       // 6144 per half-iter
#define GPT      (GELEM / HTPB)         // 16 per thread
#define HBUF     (2 * 48 * RST)         // V+S footprint per half

// smem layout (float offsets, float4-aligned)
#define SO_X    0                       // 9600 : x-knots
#define SO_Q    (SO_X + 48*200)         // 9600 : [j][i]
#define SO_QT   (SO_Q  + 48*48)         // 11904 : [i][j]
#define SO_V0   (SO_QT + 48*48)         // 14208 : half-0 V (becomes V+W)
#define SO_S0   (SO_V0 + 48*RST)        // 20544 : half-0 S
#define SO_V1   (SO_S0 + 48*RST)        // 26880 : half-1 V
#define SO_S1   (SO_V1 + 48*RST)        // 33216 : half-1 S
#define SO_LJ   (SO_S1 + 48*RST)        // 39552 : [2][12][128]
#define SO_XLO  (SO_LJ + 2*12*128)      // 42624
#define SO_IVW  (SO_XLO + 48)           // 42672
#define SO_RI   (SO_IVW + 48)           // 42720
#define SO_LUT  (SO_RI + 48)            // 42768 : uint8[12288]
#define SMEM_FLOATS (SO_LUT + 3072)     // 45840
#define SMEM_BYTES  (SMEM_FLOATS * 4)   // 183,360 B

__device__ __forceinline__ float rq_eval(float x,
                                         const float* __restrict__ xr,
                                         const float2* __restrict__ yd,   // global (L2)
                                         const unsigned char* __restrict__ lut,
                                         float xlo, float ivw, float& dv) {
    int q = __float2int_rd((x - xlo) * ivw);
    q = min(max(q, 0), 255);
    int idx = lut[q];
    while (idx > 0 && xr[idx - 1] >= x) --idx;
    while (idx < MKNOT && xr[idx] < x) ++idx;
    if (idx == 0) {
        float2 k0 = __ldg(&yd[0]);
        dv = k0.y;
        return k0.x + dv * (x - xr[0]);
    }
    if (idx == MKNOT) {
        float2 km = __ldg(&yd[MKNOT - 1]);
        dv = km.y;
        return km.x + dv * (x - xr[MKNOT - 1]);
    }
    const int kk = idx - 1;
    const float  xK = xr[kk], xK1 = xr[kk + 1];
    const float2 k0 = __ldg(&yd[kk]);
    const float2 k1 = __ldg(&yd[kk + 1]);
    const float inv = __fdividef(1.f, xK1 - xK);
    float xi = fminf(fmaxf((x - xK) * inv, 0.f), 1.f);
    const float sl  = (k1.x - k0.x) * inv;
    const float xi1 = xi * (1.f - xi);
    const float den = sl + (k1.y + k0.y - 2.f * sl) * xi1;
    const float ivd = __fdividef(1.f, den);
    const float om  = 1.f - xi;
    dv = sl * sl * (k1.y * xi * xi + 2.f * sl * xi1 + k0.y * om * om) * ivd * ivd;
    return k0.x + (k1.x - k0.x) * (sl * xi * xi + k0.y * xi1) * ivd;
}

__global__ void __launch_bounds__(TPB, 1)
fused_kernel(const float* __restrict__ data, float* __restrict__ out) {
    extern __shared__ float sm[];
    int* ri = (int*)&sm[SO_RI];
    unsigned char* slut = (unsigned char*)&sm[SO_LUT];

    const int tid = threadIdx.x;
    const int k   = blockIdx.x;

    // ---- shared prologue (all 768 threads) -----------------------------
    {
        const float4* gq  = (const float4*)(g_Q  + k * (NSUB * NSUB));
        const float4* gqt = (const float4*)(g_QT + k * (NSUB * NSUB));
        float4* sq  = (float4*)&sm[SO_Q];
        float4* sqt = (float4*)&sm[SO_QT];
        for (int idx = tid; idx < NSUB * NSUB / 4; idx += TPB) {
            sq[idx]  = gq[idx];
            sqt[idx] = gqt[idx];
        }
        const float4* gx = (const float4*)(g_xx + (size_t)k * NSUB * MKNOT);
        float4* sx = (float4*)&sm[SO_X];
        for (int idx = tid; idx < NSUB * MKNOT / 4; idx += TPB) sx[idx] = gx[idx];
        const int4* gl = (const int4*)(g_lut + (size_t)k * NSUB * 256);
        int4* sl = (int4*)slut;
        for (int idx = tid; idx < NSUB * 256 / 16; idx += TPB) sl[idx] = gl[idx];
        if (tid < NSUB) {
            sm[SO_XLO + tid] = g_lxlo[k * NSUB + tid];
            sm[SO_IVW + tid] = g_livw[k * NSUB + tid];
            int nh = k >> 3, nw = k & 7;
            int kh = tid / 12, rem = tid - kh * 12, kw = rem / 3, c = rem - kw * 3;
            int h = (nh * 4 + kh + 2) & 31;
            int w = (nw * 4 + kw + 2) & 31;
            ri[tid] = h * 96 + w * 3 + c;
        }
    }
    __syncthreads();                    // last CTA-wide barrier

    // ---- split into two free-running halves -----------------------------
    const int h  = (tid >= HTPB) ? 1 : 0;
    const int lt = tid - h * HTPB;      // 0..383
    const int SOV = SO_V0 + h * HBUF;   // private V
    const int SOS = SO_S0 + h * HBUF;   // private S

    // staging map: element e = r*48 + j (per half)
    int ge_a[GPT];                      // gmem offset within a row-block
    int ge_s[GPT];                      // smem index j*RST + r
#pragma unroll
    for (int t = 0; t < GPT; ++t) {
        unsigned int e = lt + HTPB * t;
        unsigned int r = e / 48u;
        unsigned int j = e - r * 48u;
        ge_a[t] = (int)r * NDIMT + ri[j];
        ge_s[t] = (int)(j * RST + r);
    }

    const int ig = lt >> 5;             // 0..11 (warp-uniform)
    const int rg = lt & 31;             // 0..31
    const int i0 = ig * 4;
    const int r0 = rg * 4;
    const int nb0 = blockIdx.y * (2 * ROWS_IT * ITERS) + h * (ROWS_IT * ITERS);
    const float2* ydk = g_yd + (size_t)k * NSUB * MKNOT;
    float* ljh = &sm[SO_LJ + h * 12 * 128];

    // prefetch iteration 0 of this half
    float pf[GPT];
#pragma unroll
    for (int t = 0; t < GPT; ++t)
        pf[t] = __ldg(&data[(size_t)nb0 * NDIMT + ge_a[t]]);

    for (int it = 0; it < ITERS; ++it) {
        const int nbase = nb0 + it * ROWS_IT;

        // ---- stage V from prefetch regs -------------------------------
        HALF_BAR(h);                    // previous scatter done; V free
#pragma unroll
        for (int t = 0; t < GPT; ++t)
            sm[SOV + ge_s[t]] = pf[t];
        HALF_BAR(h);

        // ---- prefetch next iter ----------------------------------------
        if (it + 1 < ITERS) {
            const float* base = &data[(size_t)(nbase + ROWS_IT) * NDIMT];
#pragma unroll
            for (int t = 0; t < GPT; ++t) pf[t] = __ldg(&base[ge_a[t]]);
        }

        // ---- fwd GEMV (i4 x r4, U in regs) + fused RQ spline ------------
        {
            unsigned long long acc[4][2] = {{0,0},{0,0},{0,0},{0,0}};
#pragma unroll 6
            for (int j = 0; j < 48; ++j) {
                const float4 q = *(const float4*)&sm[SO_Q + j * 48 + i0];   // bcast
                const ulonglong2 v = *(const ulonglong2*)&sm[SOV + j * RST + r0];
                const unsigned long long q0 = splat2(q.x), q1 = splat2(q.y);
                const unsigned long long q2 = splat2(q.z), q3 = splat2(q.w);
                ffma2(acc[0][0], q0, v.x); ffma2(acc[0][1], q0, v.y);
                ffma2(acc[1][0], q1, v.x); ffma2(acc[1][1], q1, v.y);
                ffma2(acc[2][0], q2, v.x); ffma2(acc[2][1], q2, v.y);
                ffma2(acc[3][0], q3, v.x); ffma2(acc[3][1], q3, v.y);
            }
            float pd[4] = {1.f, 1.f, 1.f, 1.f};
#pragma unroll
            for (int s = 0; s < 4; ++s) {
                const int i = i0 + s;
                const float*  xr = &sm[SO_X + i * MKNOT];
                const float2* yd = ydk + i * MKNOT;
                const unsigned char* lut = slut + i * 256;
                const float xlo = sm[SO_XLO + i];
                const float ivw = sm[SO_IVW + i];

                float2 ua = unpk2(acc[s][0]);
                float2 ub = unpk2(acc[s][1]);
                float u[4] = {ua.x, ua.y, ub.x, ub.y};
                float4 sv;
                float d0, d1, d2, d3;
                sv.x = rq_eval(u[0], xr, yd, lut, xlo, ivw, d0) - u[0];
                sv.y = rq_eval(u[1], xr, yd, lut, xlo, ivw, d1) - u[1];
                sv.z = rq_eval(u[2], xr, yd, lut, xlo, ivw, d2) - u[2];
                sv.w = rq_eval(u[3], xr, yd, lut, xlo, ivw, d3) - u[3];
                *(float4*)&sm[SOS + i * RST + r0] = sv;
                pd[0] *= d0; pd[1] *= d1; pd[2] *= d2; pd[3] *= d3;
            }
            float4 lj4;
            lj4.x = __logf(pd[0]); lj4.y = __logf(pd[1]);
            lj4.z = __logf(pd[2]); lj4.w = __logf(pd[3]);
            *(float4*)&ljh[ig * 128 + r0] = lj4;
        }
        HALF_BAR(h);

        // ---- bwd GEMV: W = QT*S; V += W in place ------------------------
        {
            unsigned long long acc[4][2] = {{0,0},{0,0},{0,0},{0,0}};
            const int j0 = i0;
#pragma unroll 6
            for (int i = 0; i < 48; ++i) {
                const float4 q = *(const float4*)&sm[SO_QT + i * 48 + j0];  // bcast
                const ulonglong2 v = *(const ulonglong2*)&sm[SOS + i * RST + r0];
                const unsigned long long q0 = splat2(q.x), q1 = splat2(q.y);
                const unsigned long long q2 = splat2(q.z), q3 = splat2(q.w);
                ffma2(acc[0][0], q0, v.x); ffma2(acc[0][1], q0, v.y);
                ffma2(acc[1][0], q1, v.x); ffma2(acc[1][1], q1, v.y);
                ffma2(acc[2][0], q2, v.x); ffma2(acc[2][1], q2, v.y);
                ffma2(acc[3][0], q3, v.x); ffma2(acc[3][1], q3, v.y);
            }
#pragma unroll
            for (int p = 0; p < 4; ++p) {
                float4* vp = (float4*)&sm[SOV + (j0 + p) * RST + r0];
                float4 v = *vp;                                   // exclusive tile
                float2 wa = unpk2(acc[p][0]);
                float2 wb = unpk2(acc[p][1]);
                v.x += wa.x; v.y += wa.y; v.z += wb.x; v.w += wb.y;
                *vp = v;
            }
        }
        HALF_BAR(h);

        // ---- scatter (V holds V+W) + per-row logdet partials ------------
        {
            float* obase = &out[(size_t)nbase * NDIMT];
#pragma unroll
            for (int t = 0; t < GPT; ++t)
                obase[ge_a[t]] = sm[SOV + ge_s[t]];
            if (lt < ROWS_IT) {
                float s = 0.f;
#pragma unroll
                for (int g = 0; g < 12; ++g) s += ljh[g * 128 + lt];
                g_lj[(size_t)k * NSAMP + nbase + lt] = s;
            }
        }
    }
}

// ---------------------------------------------------------------------------
// Kernel 4: deterministic logdet reduction.
// ---------------------------------------------------------------------------
__global__ void reduce_lj(float* __restrict__ logj) {
    int n = blockIdx.x * blockDim.x + threadIdx.x;
    if (n >= NSAMP) return;
    float s = 0.f;
#pragma unroll
    for (int k = 0; k < NKER; ++k) s += g_lj[(size_t)k * NSAMP + n];
    logj[n] = s;
}

// ---------------------------------------------------------------------------
// Launch
// ---------------------------------------------------------------------------
extern "C" void kernel_launch(void* const* d_in, const int* in_sizes, int n_in,
                              void* d_out, int out_size) {
    const float* data     = (const float*)d_in[0];
    const float* A_raw    = (const float*)d_in[1];
    const float* x0       = (const float*)d_in[2];
    const float* logdx    = (const float*)d_in[3];
    const float* y0       = (const float*)d_in[4];
    const float* logdy    = (const float*)d_in[5];
    const float* logderiv = (const float*)d_in[6];

    float* out  = (float*)d_out;
    float* logj = out + (size_t)NSAMP * NDIMT;

    cudaFuncSetAttribute(fused_kernel,
                         cudaFuncAttributeMaxDynamicSharedMemorySize, SMEM_BYTES);

    orth_kernel<<<NKER, 64>>>(A_raw);
    knots_kernel<<<NTRT / 4, 128>>>(x0, logdx, y0, logdy, logderiv);
    lut_kernel<<<NTRT / 8, 256>>>();
    fused_kernel<<<dim3(NKER, 16), TPB, SMEM_BYTES>>>(data, out);
    reduce_lj<<<(NSAMP + 255) / 256, 256>>>(logj);
}

// round 15
// speedup vs baseline: 1.0395x; 1.0395x over previous
#include <cuda_runtime.h>
#include <math.h>
#include <stdint.h>

// ---------------------------------------------------------------------------
// Problem constants
// ---------------------------------------------------------------------------
#define NSAMP  8192
#define NDIMT  3072
#define NKER   64
#define NSUB   48
#define MKNOT  200
#define NTRT   3072

// ---------------------------------------------------------------------------
// Device scratch (static only)
// ---------------------------------------------------------------------------
__device__ float  g_Q  [NKER * NSUB * NSUB];   // [k][j][i]
__device__ float  g_QT [NKER * NSUB * NSUB];   // [k][i][j]
__device__ float  g_xx [NTRT * MKNOT];         // x knots
__device__ float2 g_yd [NTRT * MKNOT];         // (y, d) knots, interleaved
__device__ float  g_lj [NKER * NSAMP];
__device__ unsigned char g_lut[NTRT * 256];
__device__ float  g_lxlo[NTRT];
__device__ float  g_livw[NTRT];

// ---------------------------------------------------------------------------
// f32x2 helpers (packed fp32 — exact fp32 per lane)
// ---------------------------------------------------------------------------
__device__ __forceinline__ void ffma2(unsigned long long& acc,
                                      unsigned long long a, unsigned long long b) {
    asm("fma.rn.f32x2 %0, %1, %2, %0;" : "+l"(acc) : "l"(a), "l"(b));
}
__device__ __forceinline__ unsigned long long splat2(float v) {
    unsigned long long r;
    asm("mov.b64 %0, {%1, %1};" : "=l"(r) : "f"(v));
    return r;
}
__device__ __forceinline__ float2 unpk2(unsigned long long v) {
    float2 r;
    asm("mov.b64 {%0, %1}, %2;" : "=f"(r.x), "=f"(r.y) : "l"(v));
    return r;
}

// ---------------------------------------------------------------------------
// Kernel 1 (merged prep): blocks 0..63 -> per-patch MGS QR;
// blocks 64..831 -> knot-table warp scans. One launch, overlapped execution.
// ---------------------------------------------------------------------------
#define ORTH_BLOCKS 64
#define KNOT_BLOCKS 768                 // 3072 warps / 4 per block
#define PREP_TPB    128

__device__ void orth_body(const float* __restrict__ A_raw, int k, int tid) {
    __shared__ float qcol[NSUB];

    float col[NSUB];
    const float* Ab = A_raw + k * (NSUB * NSUB);
    if (tid < NSUB) {
#pragma unroll
        for (int r = 0; r < NSUB; ++r) col[r] = Ab[r * NSUB + tid];
    }

    for (int c = 0; c < NSUB; ++c) {
        if (tid == c) {
            float nrm = 0.f;
#pragma unroll
            for (int r = 0; r < NSUB; ++r) nrm += col[r] * col[r];
            float inv = 1.0f / sqrtf(nrm);
#pragma unroll
            for (int r = 0; r < NSUB; ++r) { col[r] *= inv; qcol[r] = col[r]; }
        }
        __syncthreads();
        if (tid < NSUB) {
            if (tid == c) {
                float* gq  = g_Q  + k * (NSUB * NSUB);
                float* gqt = g_QT + k * (NSUB * NSUB);
#pragma unroll
                for (int r = 0; r < NSUB; ++r) {
                    gq [r * NSUB + c] = qcol[r];
                    gqt[c * NSUB + r] = qcol[r];
                }
            } else if (tid > c) {
                float dot = 0.f;
#pragma unroll
                for (int r = 0; r < NSUB; ++r) dot += qcol[r] * col[r];
#pragma unroll
                for (int r = 0; r < NSUB; ++r) col[r] -= dot * qcol[r];
            }
        }
        __syncthreads();
    }
}

__device__ void knots_body(const float* __restrict__ x0,
                           const float* __restrict__ logdx,
                           const float* __restrict__ y0,
                           const float* __restrict__ logdy,
                           const float* __restrict__ logderiv,
                           int warp, int lane) {
    {
        float carry = x0[warp];
        if (lane == 0) g_xx[warp * MKNOT] = carry;
        const float* src = logdx + (size_t)warp * (MKNOT - 1);
        for (int c = 0; c < MKNOT - 1; c += 32) {
            int m = c + lane;
            float v = (m < MKNOT - 1) ? expf(src[m]) : 0.f;
#pragma unroll
            for (int off = 1; off < 32; off <<= 1) {
                float o = __shfl_up_sync(0xffffffffu, v, off);
                if (lane >= off) v += o;
            }
            if (m < MKNOT - 1) g_xx[warp * MKNOT + m + 1] = carry + v;
            carry += __shfl_sync(0xffffffffu, v, 31);
        }
    }
    {
        float carry = y0[warp];
        if (lane == 0) g_yd[warp * MKNOT].x = carry;
        const float* src = logdy + (size_t)warp * (MKNOT - 1);
        for (int c = 0; c < MKNOT - 1; c += 32) {
            int m = c + lane;
            float v = (m < MKNOT - 1) ? expf(src[m]) : 0.f;
#pragma unroll
            for (int off = 1; off < 32; off <<= 1) {
                float o = __shfl_up_sync(0xffffffffu, v, off);
                if (lane >= off) v += o;
            }
            if (m < MKNOT - 1) g_yd[warp * MKNOT + m + 1].x = carry + v;
            carry += __shfl_sync(0xffffffffu, v, 31);
        }
    }
    for (int m = lane; m < MKNOT; m += 32)
        g_yd[warp * MKNOT + m].y = expf(logderiv[(size_t)warp * MKNOT + m]);
}

__global__ void prep_kernel(const float* __restrict__ A_raw,
                            const float* __restrict__ x0,
                            const float* __restrict__ logdx,
                            const float* __restrict__ y0,
                            const float* __restrict__ logdy,
                            const float* __restrict__ logderiv) {
    if (blockIdx.x < ORTH_BLOCKS) {
        orth_body(A_raw, blockIdx.x, threadIdx.x);
    } else {
        const int warp = (blockIdx.x - ORTH_BLOCKS) * (PREP_TPB / 32) + (threadIdx.x >> 5);
        const int lane = threadIdx.x & 31;
        if (warp < NTRT)
            knots_body(x0, logdx, y0, logdy, logderiv, warp, lane);
    }
}

// ---------------------------------------------------------------------------
// Kernel 2b: per-coordinate 256-bin search LUT.
// ---------------------------------------------------------------------------
__global__ void lut_kernel() {
    const int warp = (blockIdx.x * blockDim.x + threadIdx.x) >> 5;
    const int lane = threadIdx.x & 31;
    if (warp >= NTRT) return;
    const float* xr = g_xx + (size_t)warp * MKNOT;
    float xlo = xr[0], xhi = xr[MKNOT - 1];
    float binw = (xhi - xlo) * (1.0f / 256.0f);
    if (lane == 0) { g_lxlo[warp] = xlo; g_livw[warp] = 256.0f / (xhi - xlo); }
#pragma unroll
    for (int t = 0; t < 8; ++t) {
        int q = lane + 32 * t;
        float L = xlo + q * binw;
        int lo = 0, hi = MKNOT;
        while (lo < hi) { int mid = (lo + hi) >> 1; if (xr[mid] < L) lo = mid + 1; else hi = mid; }
        g_lut[(size_t)warp * 256 + q] = (unsigned char)lo;
    }
}

// ---------------------------------------------------------------------------
// Kernel 3: fused pipeline. 768 threads, i4 x r4 register tiles, 256 rows/iter.
// (identical to the best verified configuration)
// ---------------------------------------------------------------------------
#define TPB      768
#define ROWS_IT  256
#define ITERS    2
#define RST      260                    // padded row stride (260 % 4 == 0)
#define GELEM    (NSUB * ROWS_IT)       // 12288 staged elements
#define GPT      (GELEM / TPB)          // 16 per thread

// smem layout (float offsets, all float4-aligned)
#define SO_X   0                        // 48*200 x-knots
#define SO_Q   (SO_X + 48*200)          // 9600 : [j][i]
#define SO_QT  (SO_Q  + 48*48)          // 11904 : [i][j]
#define SO_V   (SO_QT + 48*48)          // 14208 : gather buffer (becomes V+W)
#define SO_S   (SO_V  + 48*RST)         // 26688 : spline output
#define SO_LJ  (SO_S  + 48*RST)         // 39168 : [12][256]
#define SO_XLO (SO_LJ + 12*256)         // 42240
#define SO_IVW (SO_XLO + 48)            // 42288
#define SO_RI  (SO_IVW + 48)            // 42336
#define SO_LUT (SO_RI + 48)             // 42384 : uint8[12288]
#define SMEM_FLOATS (SO_LUT + 3072)     // 45456
#define SMEM_BYTES  (SMEM_FLOATS * 4)   // 181,824 B

__device__ __forceinline__ float rq_eval(float x,
                                         const float* __restrict__ xr,
                                         const float2* __restrict__ yd,   // global (L2)
                                         const unsigned char* __restrict__ lut,
                                         float xlo, float ivw, float& dv) {
    int q = __float2int_rd((x - xlo) * ivw);
    q = min(max(q, 0), 255);
    int idx = lut[q];
    while (idx > 0 && xr[idx - 1] >= x) --idx;
    while (idx < MKNOT && xr[idx] < x) ++idx;
    if (idx == 0) {
        float2 k0 = __ldg(&yd[0]);
        dv = k0.y;
        return k0.x + dv * (x - xr[0]);
    }
    if (idx == MKNOT) {
        float2 km = __ldg(&yd[MKNOT - 1]);
        dv = km.y;
        return km.x + dv * (x - xr[MKNOT - 1]);
    }
    const int kk = idx - 1;
    const float  xK = xr[kk], xK1 = xr[kk + 1];
    const float2 k0 = __ldg(&yd[kk]);
    const float2 k1 = __ldg(&yd[kk + 1]);
    const float inv = __fdividef(1.f, xK1 - xK);
    float xi = fminf(fmaxf((x - xK) * inv, 0.f), 1.f);
    const float sl  = (k1.x - k0.x) * inv;
    const float xi1 = xi * (1.f - xi);
    const float den = sl + (k1.y + k0.y - 2.f * sl) * xi1;
    const float ivd = __fdividef(1.f, den);
    const float om  = 1.f - xi;
    dv = sl * sl * (k1.y * xi * xi + 2.f * sl * xi1 + k0.y * om * om) * ivd * ivd;
    return k0.x + (k1.x - k0.x) * (sl * xi * xi + k0.y * xi1) * ivd;
}

__global__ void __launch_bounds__(TPB, 1)
fused_kernel(const float* __restrict__ data, float* __restrict__ out) {
    extern __shared__ float sm[];
    int* ri = (int*)&sm[SO_RI];
    unsigned char* slut = (unsigned char*)&sm[SO_LUT];

    const int tid = threadIdx.x;
    const int k   = blockIdx.x;

    // ---- prologue --------------------------------------------------------
    {
        const float4* gq  = (const float4*)(g_Q  + k * (NSUB * NSUB));
        const float4* gqt = (const float4*)(g_QT + k * (NSUB * NSUB));
        float4* sq  = (float4*)&sm[SO_Q];
        float4* sqt = (float4*)&sm[SO_QT];
        for (int idx = tid; idx < NSUB * NSUB / 4; idx += TPB) {
            sq[idx]  = gq[idx];
            sqt[idx] = gqt[idx];
        }
        const float4* gx = (const float4*)(g_xx + (size_t)k * NSUB * MKNOT);
        float4* sx = (float4*)&sm[SO_X];
        for (int idx = tid; idx < NSUB * MKNOT / 4; idx += TPB) sx[idx] = gx[idx];
        const int4* gl = (const int4*)(g_lut + (size_t)k * NSUB * 256);
        int4* sl = (int4*)slut;
        for (int idx = tid; idx < NSUB * 256 / 16; idx += TPB) sl[idx] = gl[idx];
        if (tid < NSUB) {
            sm[SO_XLO + tid] = g_lxlo[k * NSUB + tid];
            sm[SO_IVW + tid] = g_livw[k * NSUB + tid];
            int nh = k >> 3, nw = k & 7;
            int kh = tid / 12, rem = tid - kh * 12, kw = rem / 3, c = rem - kw * 3;
            int h = (nh * 4 + kh + 2) & 31;
            int w = (nw * 4 + kw + 2) & 31;
            ri[tid] = h * 96 + w * 3 + c;
        }
    }
    __syncthreads();

    // staging map: element e = r*48 + j. Precompute BOTH the gmem offset and
    // the smem index (no div/mod in the hot loops).
    int ge_a[GPT];                      // gmem offset within a row-block
    int ge_s[GPT];                      // smem index j*RST + r
#pragma unroll
    for (int t = 0; t < GPT; ++t) {
        unsigned int e = tid + TPB * t;
        unsigned int r = e / 48u;
        unsigned int j = e - r * 48u;
        ge_a[t] = (int)r * NDIMT + ri[j];
        ge_s[t] = (int)(j * RST + r);
    }

    const int ig = tid >> 6;            // 0..11 : i/j tile group (4 wide)
    const int rg = tid & 63;            // 0..63 : r tile group (4 wide)
    const int i0 = ig * 4;
    const int r0 = rg * 4;
    const int nb0 = blockIdx.y * (ROWS_IT * ITERS);
    const float2* ydk = g_yd + (size_t)k * NSUB * MKNOT;

    // prefetch iteration 0
    float pf[GPT];
#pragma unroll
    for (int t = 0; t < GPT; ++t)
        pf[t] = __ldg(&data[(size_t)nb0 * NDIMT + ge_a[t]]);

    for (int it = 0; it < ITERS; ++it) {
        const int nbase = nb0 + it * ROWS_IT;

        // ---- stage V from prefetch regs -----------------------------------
        __syncthreads();                 // previous scatter done; V free
#pragma unroll
        for (int t = 0; t < GPT; ++t)
            sm[SO_V + ge_s[t]] = pf[t];
        __syncthreads();

        // ---- prefetch next iter (hidden behind GEMV + spline) -------------
        if (it + 1 < ITERS) {
            const float* base = &data[(size_t)(nbase + ROWS_IT) * NDIMT];
#pragma unroll
            for (int t = 0; t < GPT; ++t) pf[t] = __ldg(&base[ge_a[t]]);
        }

        // ---- fwd GEMV (i4 x r4, U in regs) + fused RQ spline ---------------
        {
            unsigned long long acc[4][2] = {{0,0},{0,0},{0,0},{0,0}};
#pragma unroll 6
            for (int j = 0; j < 48; ++j) {
                const float4 q = *(const float4*)&sm[SO_Q + j * 48 + i0];       // bcast
                const ulonglong2 v = *(const ulonglong2*)&sm[SO_V + j * RST + r0];
                const unsigned long long q0 = splat2(q.x), q1 = splat2(q.y);
                const unsigned long long q2 = splat2(q.z), q3 = splat2(q.w);
                ffma2(acc[0][0], q0, v.x); ffma2(acc[0][1], q0, v.y);
                ffma2(acc[1][0], q1, v.x); ffma2(acc[1][1], q1, v.y);
                ffma2(acc[2][0], q2, v.x); ffma2(acc[2][1], q2, v.y);
                ffma2(acc[3][0], q3, v.x); ffma2(acc[3][1], q3, v.y);
            }
            float pd[4] = {1.f, 1.f, 1.f, 1.f};   // product of d per r-lane
#pragma unroll
            for (int s = 0; s < 4; ++s) {
                const int i = i0 + s;
                const float*  xr = &sm[SO_X + i * MKNOT];
                const float2* yd = ydk + i * MKNOT;
                const unsigned char* lut = slut + i * 256;
                const float xlo = sm[SO_XLO + i];
                const float ivw = sm[SO_IVW + i];

                float2 ua = unpk2(acc[s][0]);
                float2 ub = unpk2(acc[s][1]);
                float u[4] = {ua.x, ua.y, ub.x, ub.y};
                float4 sv;
                float d0, d1, d2, d3;
                sv.x = rq_eval(u[0], xr, yd, lut, xlo, ivw, d0) - u[0];
                sv.y = rq_eval(u[1], xr, yd, lut, xlo, ivw, d1) - u[1];
                sv.z = rq_eval(u[2], xr, yd, lut, xlo, ivw, d2) - u[2];
                sv.w = rq_eval(u[3], xr, yd, lut, xlo, ivw, d3) - u[3];
                *(float4*)&sm[SO_S + i * RST + r0] = sv;
                pd[0] *= d0; pd[1] *= d1; pd[2] *= d2; pd[3] *= d3;
            }
            // one log per r-lane (log of product == sum of logs to fp32 rounding)
            float4 lj4;
            lj4.x = __logf(pd[0]); lj4.y = __logf(pd[1]);
            lj4.z = __logf(pd[2]); lj4.w = __logf(pd[3]);
            *(float4*)&sm[SO_LJ + ig * 256 + r0] = lj4;
        }
        __syncthreads();

        // ---- bwd GEMV: W[j][r] = sum_i QT[i][j]*S[i][r]; V += W in place ---
        {
            unsigned long long acc[4][2] = {{0,0},{0,0},{0,0},{0,0}};
            const int j0 = i0;
#pragma unroll 6
            for (int i = 0; i < 48; ++i) {
                const float4 q = *(const float4*)&sm[SO_QT + i * 48 + j0];      // bcast
                const ulonglong2 v = *(const ulonglong2*)&sm[SO_S + i * RST + r0];
                const unsigned long long q0 = splat2(q.x), q1 = splat2(q.y);
                const unsigned long long q2 = splat2(q.z), q3 = splat2(q.w);
                ffma2(acc[0][0], q0, v.x); ffma2(acc[0][1], q0, v.y);
                ffma2(acc[1][0], q1, v.x); ffma2(acc[1][1], q1, v.y);
                ffma2(acc[2][0], q2, v.x); ffma2(acc[2][1], q2, v.y);
                ffma2(acc[3][0], q3, v.x); ffma2(acc[3][1], q3, v.y);
            }
#pragma unroll
            for (int p = 0; p < 4; ++p) {
                float4* vp = (float4*)&sm[SO_V + (j0 + p) * RST + r0];
                float4 v = *vp;                                   // exclusive tile
                float2 wa = unpk2(acc[p][0]);
                float2 wb = unpk2(acc[p][1]);
                v.x += wa.x; v.y += wa.y; v.z += wb.x; v.w += wb.y;
                *vp = v;
            }
        }
        __syncthreads();

        // ---- scatter (V holds V+W) + per-row logdet partials ---------------
        {
            float* obase = &out[(size_t)nbase * NDIMT];
#pragma unroll
            for (int t = 0; t < GPT; ++t)
                obase[ge_a[t]] = sm[SO_V + ge_s[t]];
            if (tid < ROWS_IT) {
                float s = 0.f;
#pragma unroll
                for (int g = 0; g < 12; ++g) s += sm[SO_LJ + g * 256 + tid];
                g_lj[(size_t)k * NSAMP + nbase + tid] = s;
            }
        }
    }
}

// ---------------------------------------------------------------------------
// Kernel 4: deterministic logdet reduction (8 rotating accumulators for MLP).
// ---------------------------------------------------------------------------
__global__ void reduce_lj(float* __restrict__ logj) {
    int n = blockIdx.x * blockDim.x + threadIdx.x;
    if (n >= NSAMP) return;
    float s[8] = {0.f, 0.f, 0.f, 0.f, 0.f, 0.f, 0.f, 0.f};
#pragma unroll
    for (int k = 0; k < NKER; ++k)
        s[k & 7] += __ldg(&g_lj[(size_t)k * NSAMP + n]);
    logj[n] = ((s[0] + s[1]) + (s[2] + s[3])) + ((s[4] + s[5]) + (s[6] + s[7]));
}

// ---------------------------------------------------------------------------
// Launch
// ---------------------------------------------------------------------------
extern "C" void kernel_launch(void* const* d_in, const int* in_sizes, int n_in,
                              void* d_out, int out_size) {
    const float* data     = (const float*)d_in[0];
    const float* A_raw    = (const float*)d_in[1];
    const float* x0       = (const float*)d_in[2];
    const float* logdx    = (const float*)d_in[3];
    const float* y0       = (const float*)d_in[4];
    const float* logdy    = (const float*)d_in[5];
    const float* logderiv = (const float*)d_in[6];

    float* out  = (float*)d_out;
    float* logj = out + (size_t)NSAMP * NDIMT;

    cudaFuncSetAttribute(fused_kernel,
                         cudaFuncAttributeMaxDynamicSharedMemorySize, SMEM_BYTES);

    prep_kernel<<<ORTH_BLOCKS + KNOT_BLOCKS, PREP_TPB>>>(A_raw, x0, logdx,
                                                         y0, logdy, logderiv);
    lut_kernel<<<NTRT / 8, 256>>>();
    fused_kernel<<<dim3(NKER, 16), TPB, SMEM_BYTES>>>(data, out);
    reduce_lj<<<(NSAMP + 255) / 256, 256>>>(logj);
}

// round 16
// speedup vs baseline: 1.0686x; 1.0280x over previous
#include <cuda_runtime.h>
#include <math.h>
#include <stdint.h>

// ---------------------------------------------------------------------------
// Problem constants
// ---------------------------------------------------------------------------
#define NSAMP  8192
#define NDIMT  3072
#define NKER   64
#define NSUB   48
#define MKNOT  200
#define NTRT   3072

// ---------------------------------------------------------------------------
// Device scratch (static only)
// ---------------------------------------------------------------------------
__device__ float  g_Q  [NKER * NSUB * NSUB];   // [k][j][i]
__device__ float  g_QT [NKER * NSUB * NSUB];   // [k][i][j]
__device__ float  g_xx [NTRT * MKNOT];         // x knots
__device__ float2 g_yd [NTRT * MKNOT];         // (y, d) knots, interleaved
__device__ float  g_lj [NKER * NSAMP];
__device__ unsigned char g_lut[NTRT * 256];
__device__ float  g_lxlo[NTRT];
__device__ float  g_livw[NTRT];

// ---------------------------------------------------------------------------
// f32x2 helpers (packed fp32 — exact fp32 per lane)
// ---------------------------------------------------------------------------
__device__ __forceinline__ void ffma2(unsigned long long& acc,
                                      unsigned long long a, unsigned long long b) {
    asm("fma.rn.f32x2 %0, %1, %2, %0;" : "+l"(acc) : "l"(a), "l"(b));
}
__device__ __forceinline__ unsigned long long splat2(float v) {
    unsigned long long r;
    asm("mov.b64 %0, {%1, %1};" : "=l"(r) : "f"(v));
    return r;
}
__device__ __forceinline__ float2 unpk2(unsigned long long v) {
    float2 r;
    asm("mov.b64 {%0, %1}, %2;" : "=f"(r.x), "=f"(r.y) : "l"(v));
    return r;
}

// ---------------------------------------------------------------------------
// Kernel 1 (merged prep): blocks 0..63 -> per-patch MGS QR;
// blocks 64..831 -> knot scans + per-coordinate LUT (built from smem x-knots).
// ---------------------------------------------------------------------------
#define ORTH_BLOCKS 64
#define KNOT_BLOCKS 768                 // 3072 warps / 4 per block
#define PREP_TPB    128

__device__ void orth_body(const float* __restrict__ A_raw, int k, int tid) {
    __shared__ float qcol[NSUB];

    float col[NSUB];
    const float* Ab = A_raw + k * (NSUB * NSUB);
    if (tid < NSUB) {
#pragma unroll
        for (int r = 0; r < NSUB; ++r) col[r] = Ab[r * NSUB + tid];
    }

    for (int c = 0; c < NSUB; ++c) {
        if (tid == c) {
            float nrm = 0.f;
#pragma unroll
            for (int r = 0; r < NSUB; ++r) nrm += col[r] * col[r];
            float inv = 1.0f / sqrtf(nrm);
#pragma unroll
            for (int r = 0; r < NSUB; ++r) { col[r] *= inv; qcol[r] = col[r]; }
        }
        __syncthreads();
        if (tid < NSUB) {
            if (tid == c) {
                float* gq  = g_Q  + k * (NSUB * NSUB);
                float* gqt = g_QT + k * (NSUB * NSUB);
#pragma unroll
                for (int r = 0; r < NSUB; ++r) {
                    gq [r * NSUB + c] = qcol[r];
                    gqt[c * NSUB + r] = qcol[r];
                }
            } else if (tid > c) {
                float dot = 0.f;
#pragma unroll
                for (int r = 0; r < NSUB; ++r) dot += qcol[r] * col[r];
#pragma unroll
                for (int r = 0; r < NSUB; ++r) col[r] -= dot * qcol[r];
            }
        }
        __syncthreads();
    }
}

__device__ void knots_body(const float* __restrict__ x0,
                           const float* __restrict__ logdx,
                           const float* __restrict__ y0,
                           const float* __restrict__ logdy,
                           const float* __restrict__ logderiv,
                           int warp, int lane, float* __restrict__ xb) {
    // ---- x scan (also stash knots in smem for the LUT pass) ------------
    {
        float carry = x0[warp];
        if (lane == 0) { g_xx[warp * MKNOT] = carry; xb[0] = carry; }
        const float* src = logdx + (size_t)warp * (MKNOT - 1);
        for (int c = 0; c < MKNOT - 1; c += 32) {
            int m = c + lane;
            float v = (m < MKNOT - 1) ? expf(src[m]) : 0.f;
#pragma unroll
            for (int off = 1; off < 32; off <<= 1) {
                float o = __shfl_up_sync(0xffffffffu, v, off);
                if (lane >= off) v += o;
            }
            if (m < MKNOT - 1) {
                float xv = carry + v;
                g_xx[warp * MKNOT + m + 1] = xv;
                xb[m + 1] = xv;
            }
            carry += __shfl_sync(0xffffffffu, v, 31);
        }
    }
    __syncwarp();

    // ---- LUT from smem x-knots (identical semantics to old lut_kernel) --
    {
        float xlo = xb[0], xhi = xb[MKNOT - 1];
        float binw = (xhi - xlo) * (1.0f / 256.0f);
        if (lane == 0) { g_lxlo[warp] = xlo; g_livw[warp] = 256.0f / (xhi - xlo); }
#pragma unroll
        for (int t = 0; t < 8; ++t) {
            int q = lane + 32 * t;
            float L = xlo + q * binw;
            int lo = 0, hi = MKNOT;
            while (lo < hi) { int mid = (lo + hi) >> 1; if (xb[mid] < L) lo = mid + 1; else hi = mid; }
            g_lut[(size_t)warp * 256 + q] = (unsigned char)lo;
        }
    }

    // ---- y scan ----------------------------------------------------------
    {
        float carry = y0[warp];
        if (lane == 0) g_yd[warp * MKNOT].x = carry;
        const float* src = logdy + (size_t)warp * (MKNOT - 1);
        for (int c = 0; c < MKNOT - 1; c += 32) {
            int m = c + lane;
            float v = (m < MKNOT - 1) ? expf(src[m]) : 0.f;
#pragma unroll
            for (int off = 1; off < 32; off <<= 1) {
                float o = __shfl_up_sync(0xffffffffu, v, off);
                if (lane >= off) v += o;
            }
            if (m < MKNOT - 1) g_yd[warp * MKNOT + m + 1].x = carry + v;
            carry += __shfl_sync(0xffffffffu, v, 31);
        }
    }
    // ---- delta -----------------------------------------------------------
    for (int m = lane; m < MKNOT; m += 32)
        g_yd[warp * MKNOT + m].y = expf(logderiv[(size_t)warp * MKNOT + m]);
}

__global__ void prep_kernel(const float* __restrict__ A_raw,
                            const float* __restrict__ x0,
                            const float* __restrict__ logdx,
                            const float* __restrict__ y0,
                            const float* __restrict__ logdy,
                            const float* __restrict__ logderiv) {
    if (blockIdx.x < ORTH_BLOCKS) {
        orth_body(A_raw, blockIdx.x, threadIdx.x);
    } else {
        __shared__ float xbuf[PREP_TPB / 32][MKNOT];
        const int w    = threadIdx.x >> 5;
        const int warp = (blockIdx.x - ORTH_BLOCKS) * (PREP_TPB / 32) + w;
        const int lane = threadIdx.x & 31;
        if (warp < NTRT)
            knots_body(x0, logdx, y0, logdy, logderiv, warp, lane, xbuf[w]);
    }
}

// ---------------------------------------------------------------------------
// Kernel 3: fused pipeline. 768 threads, i4 x r4 register tiles, 256 rows/iter.
// (identical to the best verified configuration)
// ---------------------------------------------------------------------------
#define TPB      768
#define ROWS_IT  256
#define ITERS    2
#define RST      260                    // padded row stride (260 % 4 == 0)
#define GELEM    (NSUB * ROWS_IT)       // 12288 staged elements
#define GPT      (GELEM / TPB)          // 16 per thread

// smem layout (float offsets, all float4-aligned)
#define SO_X   0                        // 48*200 x-knots
#define SO_Q   (SO_X + 48*200)          // 9600 : [j][i]
#define SO_QT  (SO_Q  + 48*48)          // 11904 : [i][j]
#define SO_V   (SO_QT + 48*48)          // 14208 : gather buffer (becomes V+W)
#define SO_S   (SO_V  + 48*RST)         // 26688 : spline output
#define SO_LJ  (SO_S  + 48*RST)         // 39168 : [12][256]
#define SO_XLO (SO_LJ + 12*256)         // 42240
#define SO_IVW (SO_XLO + 48)            // 42288
#define SO_RI  (SO_IVW + 48)            // 42336
#define SO_LUT (SO_RI + 48)             // 42384 : uint8[12288]
#define SMEM_FLOATS (SO_LUT + 3072)     // 45456
#define SMEM_BYTES  (SMEM_FLOATS * 4)   // 181,824 B

__device__ __forceinline__ float rq_eval(float x,
                                         const float* __restrict__ xr,
                                         const float2* __restrict__ yd,   // global (L2)
                                         const unsigned char* __restrict__ lut,
                                         float xlo, float ivw, float& dv) {
    int q = __float2int_rd((x - xlo) * ivw);
    q = min(max(q, 0), 255);
    int idx = lut[q];
    while (idx > 0 && xr[idx - 1] >= x) --idx;
    while (idx < MKNOT && xr[idx] < x) ++idx;
    if (idx == 0) {
        float2 k0 = __ldg(&yd[0]);
        dv = k0.y;
        return k0.x + dv * (x - xr[0]);
    }
    if (idx == MKNOT) {
        float2 km = __ldg(&yd[MKNOT - 1]);
        dv = km.y;
        return km.x + dv * (x - xr[MKNOT - 1]);
    }
    const int kk = idx - 1;
    const float  xK = xr[kk], xK1 = xr[kk + 1];
    const float2 k0 = __ldg(&yd[kk]);
    const float2 k1 = __ldg(&yd[kk + 1]);
    const float inv = __fdividef(1.f, xK1 - xK);
    float xi = fminf(fmaxf((x - xK) * inv, 0.f), 1.f);
    const float sl  = (k1.x - k0.x) * inv;
    const float xi1 = xi * (1.f - xi);
    const float den = sl + (k1.y + k0.y - 2.f * sl) * xi1;
    const float ivd = __fdividef(1.f, den);
    const float om  = 1.f - xi;
    dv = sl * sl * (k1.y * xi * xi + 2.f * sl * xi1 + k0.y * om * om) * ivd * ivd;
    return k0.x + (k1.x - k0.x) * (sl * xi * xi + k0.y * xi1) * ivd;
}

__global__ void __launch_bounds__(TPB, 1)
fused_kernel(const float* __restrict__ data, float* __restrict__ out) {
    extern __shared__ float sm[];
    int* ri = (int*)&sm[SO_RI];
    unsigned char* slut = (unsigned char*)&sm[SO_LUT];

    const int tid = threadIdx.x;
    const int k   = blockIdx.x;

    // ---- prologue --------------------------------------------------------
    {
        const float4* gq  = (const float4*)(g_Q  + k * (NSUB * NSUB));
        const float4* gqt = (const float4*)(g_QT + k * (NSUB * NSUB));
        float4* sq  = (float4*)&sm[SO_Q];
        float4* sqt = (float4*)&sm[SO_QT];
        for (int idx = tid; idx < NSUB * NSUB / 4; idx += TPB) {
            sq[idx]  = gq[idx];
            sqt[idx] = gqt[idx];
        }
        const float4* gx = (const float4*)(g_xx + (size_t)k * NSUB * MKNOT);
        float4* sx = (float4*)&sm[SO_X];
        for (int idx = tid; idx < NSUB * MKNOT / 4; idx += TPB) sx[idx] = gx[idx];
        const int4* gl = (const int4*)(g_lut + (size_t)k * NSUB * 256);
        int4* sl = (int4*)slut;
        for (int idx = tid; idx < NSUB * 256 / 16; idx += TPB) sl[idx] = gl[idx];
        if (tid < NSUB) {
            sm[SO_XLO + tid] = g_lxlo[k * NSUB + tid];
            sm[SO_IVW + tid] = g_livw[k * NSUB + tid];
            int nh = k >> 3, nw = k & 7;
            int kh = tid / 12, rem = tid - kh * 12, kw = rem / 3, c = rem - kw * 3;
            int h = (nh * 4 + kh + 2) & 31;
            int w = (nw * 4 + kw + 2) & 31;
            ri[tid] = h * 96 + w * 3 + c;
        }
    }
    __syncthreads();

    // staging map: element e = r*48 + j. Precompute BOTH the gmem offset and
    // the smem index (no div/mod in the hot loops).
    int ge_a[GPT];                      // gmem offset within a row-block
    int ge_s[GPT];                      // smem index j*RST + r
#pragma unroll
    for (int t = 0; t < GPT; ++t) {
        unsigned int e = tid + TPB * t;
        unsigned int r = e / 48u;
        unsigned int j = e - r * 48u;
        ge_a[t] = (int)r * NDIMT + ri[j];
        ge_s[t] = (int)(j * RST + r);
    }

    const int ig = tid >> 6;            // 0..11 : i/j tile group (4 wide)
    const int rg = tid & 63;            // 0..63 : r tile group (4 wide)
    const int i0 = ig * 4;
    const int r0 = rg * 4;
    const int nb0 = blockIdx.y * (ROWS_IT * ITERS);
    const float2* ydk = g_yd + (size_t)k * NSUB * MKNOT;

    // prefetch iteration 0
    float pf[GPT];
#pragma unroll
    for (int t = 0; t < GPT; ++t)
        pf[t] = __ldg(&data[(size_t)nb0 * NDIMT + ge_a[t]]);

    for (int it = 0; it < ITERS; ++it) {
        const int nbase = nb0 + it * ROWS_IT;

        // ---- stage V from prefetch regs -----------------------------------
        __syncthreads();                 // previous scatter done; V free
#pragma unroll
        for (int t = 0; t < GPT; ++t)
            sm[SO_V + ge_s[t]] = pf[t];
        __syncthreads();

        // ---- prefetch next iter (hidden behind GEMV + spline) -------------
        if (it + 1 < ITERS) {
            const float* base = &data[(size_t)(nbase + ROWS_IT) * NDIMT];
#pragma unroll
            for (int t = 0; t < GPT; ++t) pf[t] = __ldg(&base[ge_a[t]]);
        }

        // ---- fwd GEMV (i4 x r4, U in regs) + fused RQ spline ---------------
        {
            unsigned long long acc[4][2] = {{0,0},{0,0},{0,0},{0,0}};
#pragma unroll 6
            for (int j = 0; j < 48; ++j) {
                const float4 q = *(const float4*)&sm[SO_Q + j * 48 + i0];       // bcast
                const ulonglong2 v = *(const ulonglong2*)&sm[SO_V + j * RST + r0];
                const unsigned long long q0 = splat2(q.x), q1 = splat2(q.y);
                const unsigned long long q2 = splat2(q.z), q3 = splat2(q.w);
                ffma2(acc[0][0], q0, v.x); ffma2(acc[0][1], q0, v.y);
                ffma2(acc[1][0], q1, v.x); ffma2(acc[1][1], q1, v.y);
                ffma2(acc[2][0], q2, v.x); ffma2(acc[2][1], q2, v.y);
                ffma2(acc[3][0], q3, v.x); ffma2(acc[3][1], q3, v.y);
            }
            float pd[4] = {1.f, 1.f, 1.f, 1.f};   // product of d per r-lane
#pragma unroll
            for (int s = 0; s < 4; ++s) {
                const int i = i0 + s;
                const float*  xr = &sm[SO_X + i * MKNOT];
                const float2* yd = ydk + i * MKNOT;
                const unsigned char* lut = slut + i * 256;
                const float xlo = sm[SO_XLO + i];
                const float ivw = sm[SO_IVW + i];

                float2 ua = unpk2(acc[s][0]);
                float2 ub = unpk2(acc[s][1]);
                float u[4] = {ua.x, ua.y, ub.x, ub.y};
                float4 sv;
                float d0, d1, d2, d3;
                sv.x = rq_eval(u[0], xr, yd, lut, xlo, ivw, d0) - u[0];
                sv.y = rq_eval(u[1], xr, yd, lut, xlo, ivw, d1) - u[1];
                sv.z = rq_eval(u[2], xr, yd, lut, xlo, ivw, d2) - u[2];
                sv.w = rq_eval(u[3], xr, yd, lut, xlo, ivw, d3) - u[3];
                *(float4*)&sm[SO_S + i * RST + r0] = sv;
                pd[0] *= d0; pd[1] *= d1; pd[2] *= d2; pd[3] *= d3;
            }
            // one log per r-lane (log of product == sum of logs to fp32 rounding)
            float4 lj4;
            lj4.x = __logf(pd[0]); lj4.y = __logf(pd[1]);
            lj4.z = __logf(pd[2]); lj4.w = __logf(pd[3]);
            *(float4*)&sm[SO_LJ + ig * 256 + r0] = lj4;
        }
        __syncthreads();

        // ---- bwd GEMV: W[j][r] = sum_i QT[i][j]*S[i][r]; V += W in place ---
        {
            unsigned long long acc[4][2] = {{0,0},{0,0},{0,0},{0,0}};
            const int j0 = i0;
#pragma unroll 6
            for (int i = 0; i < 48; ++i) {
                const float4 q = *(const float4*)&sm[SO_QT + i * 48 + j0];      // bcast
                const ulonglong2 v = *(const ulonglong2*)&sm[SO_S + i * RST + r0];
                const unsigned long long q0 = splat2(q.x), q1 = splat2(q.y);
                const unsigned long long q2 = splat2(q.z), q3 = splat2(q.w);
                ffma2(acc[0][0], q0, v.x); ffma2(acc[0][1], q0, v.y);
                ffma2(acc[1][0], q1, v.x); ffma2(acc[1][1], q1, v.y);
                ffma2(acc[2][0], q2, v.x); ffma2(acc[2][1], q2, v.y);
                ffma2(acc[3][0], q3, v.x); ffma2(acc[3][1], q3, v.y);
            }
#pragma unroll
            for (int p = 0; p < 4; ++p) {
                float4* vp = (float4*)&sm[SO_V + (j0 + p) * RST + r0];
                float4 v = *vp;                                   // exclusive tile
                float2 wa = unpk2(acc[p][0]);
                float2 wb = unpk2(acc[p][1]);
                v.x += wa.x; v.y += wa.y; v.z += wb.x; v.w += wb.y;
                *vp = v;
            }
        }
        __syncthreads();

        // ---- scatter (V holds V+W) + per-row logdet partials ---------------
        {
            float* obase = &out[(size_t)nbase * NDIMT];
#pragma unroll
            for (int t = 0; t < GPT; ++t)
                obase[ge_a[t]] = sm[SO_V + ge_s[t]];
            if (tid < ROWS_IT) {
                float s = 0.f;
#pragma unroll
                for (int g = 0; g < 12; ++g) s += sm[SO_LJ + g * 256 + tid];
                g_lj[(size_t)k * NSAMP + nbase + tid] = s;
            }
        }
    }
}

// ---------------------------------------------------------------------------
// Kernel 4: parallel deterministic logdet reduction.
// 256 blocks x 256 threads; 8 threads cooperate per row (8 k's each), then a
// fixed-order smem combine -> bit-stable across replays.
// ---------------------------------------------------------------------------
__global__ void reduce_lj(float* __restrict__ logj) {
    __shared__ float sb[256];
    const int t  = threadIdx.x;
    const int n  = blockIdx.x * 32 + (t >> 3);
    const int kc = t & 7;
    float s = 0.f;
#pragma unroll
    for (int u = 0; u < 8; ++u)
        s += __ldg(&g_lj[(size_t)(kc * 8 + u) * NSAMP + n]);
    sb[t] = s;
    __syncthreads();
    if (kc == 0) {
        float r = 0.f;
#pragma unroll
        for (int u = 0; u < 8; ++u) r += sb[t + u];   // fixed order
        logj[n] = r;
    }
}

// ---------------------------------------------------------------------------
// Launch
// ---------------------------------------------------------------------------
extern "C" void kernel_launch(void* const* d_in, const int* in_sizes, int n_in,
                              void* d_out, int out_size) {
    const float* data     = (const float*)d_in[0];
    const float* A_raw    = (const float*)d_in[1];
    const float* x0       = (const float*)d_in[2];
    const float* logdx    = (const float*)d_in[3];
    const float* y0       = (const float*)d_in[4];
    const float* logdy    = (const float*)d_in[5];
    const float* logderiv = (const float*)d_in[6];

    float* out  = (float*)d_out;
    float* logj = out + (size_t)NSAMP * NDIMT;

    cudaFuncSetAttribute(fused_kernel,
                         cudaFuncAttributeMaxDynamicSharedMemorySize, SMEM_BYTES);

    prep_kernel<<<ORTH_BLOCKS + KNOT_BLOCKS, PREP_TPB>>>(A_raw, x0, logdx,
                                                         y0, logdy, logderiv);
    fused_kernel<<<dim3(NKER, 16), TPB, SMEM_BYTES>>>(data, out);
    reduce_lj<<<NSAMP / 32, 256>>>(logj);
}

// round 17
// speedup vs baseline: 1.0818x; 1.0124x over previous
#include <cuda_runtime.h>
#include <math.h>
#include <stdint.h>

// ---------------------------------------------------------------------------
// Problem constants
// ---------------------------------------------------------------------------
#define NSAMP  8192
#define NDIMT  3072
#define NKER   64
#define NSUB   48
#define MKNOT  200
#define NTRT   3072

// ---------------------------------------------------------------------------
// Device scratch (static only)
// ---------------------------------------------------------------------------
__device__ float  g_Q  [NKER * NSUB * NSUB];   // [k][j][i]
__device__ float  g_QT [NKER * NSUB * NSUB];   // [k][i][j]
__device__ float  g_xx [NTRT * MKNOT];         // x knots
__device__ float2 g_yd [NTRT * MKNOT];         // (y, d) knots, interleaved
__device__ float  g_lj [NKER * NSAMP];
__device__ unsigned char g_lut[NTRT * 256];
__device__ float  g_lxlo[NTRT];
__device__ float  g_livw[NTRT];

// ---------------------------------------------------------------------------
// f32x2 helpers (packed fp32 — exact fp32 per lane)
// ---------------------------------------------------------------------------
__device__ __forceinline__ void ffma2(unsigned long long& acc,
                                      unsigned long long a, unsigned long long b) {
    asm("fma.rn.f32x2 %0, %1, %2, %0;" : "+l"(acc) : "l"(a), "l"(b));
}
__device__ __forceinline__ unsigned long long splat2(float v) {
    unsigned long long r;
    asm("mov.b64 %0, {%1, %1};" : "=l"(r) : "f"(v));
    return r;
}
__device__ __forceinline__ float2 unpk2(unsigned long long v) {
    float2 r;
    asm("mov.b64 {%0, %1}, %2;" : "=f"(r.x), "=f"(r.y) : "l"(v));
    return r;
}

// ---------------------------------------------------------------------------
// Kernel 1 (merged prep): blocks 0..63 -> per-patch MGS QR;
// blocks 64..831 -> knot scans + per-coordinate LUT (built from smem x-knots).
// ---------------------------------------------------------------------------
#define ORTH_BLOCKS 64
#define KNOT_BLOCKS 768                 // 3072 warps / 4 per block
#define PREP_TPB    128

__device__ void orth_body(const float* __restrict__ A_raw, int k, int tid) {
    __shared__ float qcol[NSUB];

    float col[NSUB];
    const float* Ab = A_raw + k * (NSUB * NSUB);
    if (tid < NSUB) {
#pragma unroll
        for (int r = 0; r < NSUB; ++r) col[r] = Ab[r * NSUB + tid];
    }

    for (int c = 0; c < NSUB; ++c) {
        if (tid == c) {
            // 4-way ILP norm (breaks the 48-deep serial FFMA chain)
            float n0 = 0.f, n1 = 0.f, n2 = 0.f, n3 = 0.f;
#pragma unroll
            for (int r = 0; r < NSUB; r += 4) {
                n0 += col[r]     * col[r];
                n1 += col[r + 1] * col[r + 1];
                n2 += col[r + 2] * col[r + 2];
                n3 += col[r + 3] * col[r + 3];
            }
            float inv = 1.0f / sqrtf((n0 + n1) + (n2 + n3));
#pragma unroll
            for (int r = 0; r < NSUB; ++r) { col[r] *= inv; qcol[r] = col[r]; }
        }
        __syncthreads();
        if (tid < NSUB) {
            if (tid == c) {
                float* gq  = g_Q  + k * (NSUB * NSUB);
                float* gqt = g_QT + k * (NSUB * NSUB);
#pragma unroll
                for (int r = 0; r < NSUB; ++r) {
                    gq [r * NSUB + c] = qcol[r];
                    gqt[c * NSUB + r] = qcol[r];
                }
            } else if (tid > c) {
                // 4-way ILP projection dot
                float d0 = 0.f, d1 = 0.f, d2 = 0.f, d3 = 0.f;
#pragma unroll
                for (int r = 0; r < NSUB; r += 4) {
                    d0 += qcol[r]     * col[r];
                    d1 += qcol[r + 1] * col[r + 1];
                    d2 += qcol[r + 2] * col[r + 2];
                    d3 += qcol[r + 3] * col[r + 3];
                }
                float dot = (d0 + d1) + (d2 + d3);
#pragma unroll
                for (int r = 0; r < NSUB; ++r) col[r] -= dot * qcol[r];
            }
        }
        __syncthreads();
    }
}

__device__ void knots_body(const float* __restrict__ x0,
                           const float* __restrict__ logdx,
                           const float* __restrict__ y0,
                           const float* __restrict__ logdy,
                           const float* __restrict__ logderiv,
                           int warp, int lane, float* __restrict__ xb) {
    // ---- x scan (also stash knots in smem for the LUT pass) ------------
    {
        float carry = x0[warp];
        if (lane == 0) { g_xx[warp * MKNOT] = carry; xb[0] = carry; }
        const float* src = logdx + (size_t)warp * (MKNOT - 1);
        for (int c = 0; c < MKNOT - 1; c += 32) {
            int m = c + lane;
            float v = (m < MKNOT - 1) ? __expf(src[m]) : 0.f;
#pragma unroll
            for (int off = 1; off < 32; off <<= 1) {
                float o = __shfl_up_sync(0xffffffffu, v, off);
                if (lane >= off) v += o;
            }
            if (m < MKNOT - 1) {
                float xv = carry + v;
                g_xx[warp * MKNOT + m + 1] = xv;
                xb[m + 1] = xv;
            }
            carry += __shfl_sync(0xffffffffu, v, 31);
        }
    }
    __syncwarp();

    // ---- LUT from smem x-knots ------------------------------------------
    {
        float xlo = xb[0], xhi = xb[MKNOT - 1];
        float binw = (xhi - xlo) * (1.0f / 256.0f);
        if (lane == 0) { g_lxlo[warp] = xlo; g_livw[warp] = 256.0f / (xhi - xlo); }
#pragma unroll
        for (int t = 0; t < 8; ++t) {
            int q = lane + 32 * t;
            float L = xlo + q * binw;
            int lo = 0, hi = MKNOT;
            while (lo < hi) { int mid = (lo + hi) >> 1; if (xb[mid] < L) lo = mid + 1; else hi = mid; }
            g_lut[(size_t)warp * 256 + q] = (unsigned char)lo;
        }
    }

    // ---- y scan ----------------------------------------------------------
    {
        float carry = y0[warp];
        if (lane == 0) g_yd[warp * MKNOT].x = carry;
        const float* src = logdy + (size_t)warp * (MKNOT - 1);
        for (int c = 0; c < MKNOT - 1; c += 32) {
            int m = c + lane;
            float v = (m < MKNOT - 1) ? __expf(src[m]) : 0.f;
#pragma unroll
            for (int off = 1; off < 32; off <<= 1) {
                float o = __shfl_up_sync(0xffffffffu, v, off);
                if (lane >= off) v += o;
            }
            if (m < MKNOT - 1) g_yd[warp * MKNOT + m + 1].x = carry + v;
            carry += __shfl_sync(0xffffffffu, v, 31);
        }
    }
    // ---- delta -----------------------------------------------------------
    for (int m = lane; m < MKNOT; m += 32)
        g_yd[warp * MKNOT + m].y = __expf(logderiv[(size_t)warp * MKNOT + m]);
}

__global__ void prep_kernel(const float* __restrict__ A_raw,
                            const float* __restrict__ x0,
                            const float* __restrict__ logdx,
                            const float* __restrict__ y0,
                            const float* __restrict__ logdy,
                            const float* __restrict__ logderiv) {
    if (blockIdx.x < ORTH_BLOCKS) {
        orth_body(A_raw, blockIdx.x, threadIdx.x);
    } else {
        __shared__ float xbuf[PREP_TPB / 32][MKNOT];
        const int w    = threadIdx.x >> 5;
        const int warp = (blockIdx.x - ORTH_BLOCKS) * (PREP_TPB / 32) + w;
        const int lane = threadIdx.x & 31;
        if (warp < NTRT)
            knots_body(x0, logdx, y0, logdy, logderiv, warp, lane, xbuf[w]);
    }
}

// ---------------------------------------------------------------------------
// Kernel 3: fused pipeline. 768 threads, i4 x r4 register tiles, 256 rows/iter.
// (identical to the best verified configuration)
// ---------------------------------------------------------------------------
#define TPB      768
#define ROWS_IT  256
#define ITERS    2
#define RST      260                    // padded row stride (260 % 4 == 0)
#define GELEM    (NSUB * ROWS_IT)       // 12288 staged elements
#define GPT      (GELEM / TPB)          // 16 per thread

// smem layout (float offsets, all float4-aligned)
#define SO_X   0                        // 48*200 x-knots
#define SO_Q   (SO_X + 48*200)          // 9600 : [j][i]
#define SO_QT  (SO_Q  + 48*48)          // 11904 : [i][j]
#define SO_V   (SO_QT + 48*48)          // 14208 : gather buffer (becomes V+W)
#define SO_S   (SO_V  + 48*RST)         // 26688 : spline output
#define SO_LJ  (SO_S  + 48*RST)         // 39168 : [12][256]
#define SO_XLO (SO_LJ + 12*256)         // 42240
#define SO_IVW (SO_XLO + 48)            // 42288
#define SO_RI  (SO_IVW + 48)            // 42336
#define SO_LUT (SO_RI + 48)             // 42384 : uint8[12288]
#define SMEM_FLOATS (SO_LUT + 3072)     // 45456
#define SMEM_BYTES  (SMEM_FLOATS * 4)   // 181,824 B

__device__ __forceinline__ float rq_eval(float x,
                                         const float* __restrict__ xr,
                                         const float2* __restrict__ yd,   // global (L2)
                                         const unsigned char* __restrict__ lut,
                                         float xlo, float ivw, float& dv) {
    int q = __float2int_rd((x - xlo) * ivw);
    q = min(max(q, 0), 255);
    int idx = lut[q];
    while (idx > 0 && xr[idx - 1] >= x) --idx;
    while (idx < MKNOT && xr[idx] < x) ++idx;
    if (idx == 0) {
        float2 k0 = __ldg(&yd[0]);
        dv = k0.y;
        return k0.x + dv * (x - xr[0]);
    }
    if (idx == MKNOT) {
        float2 km = __ldg(&yd[MKNOT - 1]);
        dv = km.y;
        return km.x + dv * (x - xr[MKNOT - 1]);
    }
    const int kk = idx - 1;
    const float  xK = xr[kk], xK1 = xr[kk + 1];
    const float2 k0 = __ldg(&yd[kk]);
    const float2 k1 = __ldg(&yd[kk + 1]);
    const float inv = __fdividef(1.f, xK1 - xK);
    float xi = fminf(fmaxf((x - xK) * inv, 0.f), 1.f);
    const float sl  = (k1.x - k0.x) * inv;
    const float xi1 = xi * (1.f - xi);
    const float den = sl + (k1.y + k0.y - 2.f * sl) * xi1;
    const float ivd = __fdividef(1.f, den);
    const float om  = 1.f - xi;
    dv = sl * sl * (k1.y * xi * xi + 2.f * sl * xi1 + k0.y * om * om) * ivd * ivd;
    return k0.x + (k1.x - k0.x) * (sl * xi * xi + k0.y * xi1) * ivd;
}

__global__ void __launch_bounds__(TPB, 1)
fused_kernel(const float* __restrict__ data, float* __restrict__ out) {
    extern __shared__ float sm[];
    int* ri = (int*)&sm[SO_RI];
    unsigned char* slut = (unsigned char*)&sm[SO_LUT];

    const int tid = threadIdx.x;
    const int k   = blockIdx.x;

    // ---- prologue --------------------------------------------------------
    {
        const float4* gq  = (const float4*)(g_Q  + k * (NSUB * NSUB));
        const float4* gqt = (const float4*)(g_QT + k * (NSUB * NSUB));
        float4* sq  = (float4*)&sm[SO_Q];
        float4* sqt = (float4*)&sm[SO_QT];
        for (int idx = tid; idx < NSUB * NSUB / 4; idx += TPB) {
            sq[idx]  = gq[idx];
            sqt[idx] = gqt[idx];
        }
        const float4* gx = (const float4*)(g_xx + (size_t)k * NSUB * MKNOT);
        float4* sx = (float4*)&sm[SO_X];
        for (int idx = tid; idx < NSUB * MKNOT / 4; idx += TPB) sx[idx] = gx[idx];
        const int4* gl = (const int4*)(g_lut + (size_t)k * NSUB * 256);
        int4* sl = (int4*)slut;
        for (int idx = tid; idx < NSUB * 256 / 16; idx += TPB) sl[idx] = gl[idx];
        if (tid < NSUB) {
            sm[SO_XLO + tid] = g_lxlo[k * NSUB + tid];
            sm[SO_IVW + tid] = g_livw[k * NSUB + tid];
            int nh = k >> 3, nw = k & 7;
            int kh = tid / 12, rem = tid - kh * 12, kw = rem / 3, c = rem - kw * 3;
            int h = (nh * 4 + kh + 2) & 31;
            int w = (nw * 4 + kw + 2) & 31;
            ri[tid] = h * 96 + w * 3 + c;
        }
    }
    __syncthreads();

    // staging map: element e = r*48 + j. Precompute BOTH the gmem offset and
    // the smem index (no div/mod in the hot loops).
    int ge_a[GPT];                      // gmem offset within a row-block
    int ge_s[GPT];                      // smem index j*RST + r
#pragma unroll
    for (int t = 0; t < GPT; ++t) {
        unsigned int e = tid + TPB * t;
        unsigned int r = e / 48u;
        unsigned int j = e - r * 48u;
        ge_a[t] = (int)r * NDIMT + ri[j];
        ge_s[t] = (int)(j * RST + r);
    }

    const int ig = tid >> 6;            // 0..11 : i/j tile group (4 wide)
    const int rg = tid & 63;            // 0..63 : r tile group (4 wide)
    const int i0 = ig * 4;
    const int r0 = rg * 4;
    const int nb0 = blockIdx.y * (ROWS_IT * ITERS);
    const float2* ydk = g_yd + (size_t)k * NSUB * MKNOT;

    // prefetch iteration 0
    float pf[GPT];
#pragma unroll
    for (int t = 0; t < GPT; ++t)
        pf[t] = __ldg(&data[(size_t)nb0 * NDIMT + ge_a[t]]);

    for (int it = 0; it < ITERS; ++it) {
        const int nbase = nb0 + it * ROWS_IT;

        // ---- stage V from prefetch regs -----------------------------------
        __syncthreads();                 // previous scatter done; V free
#pragma unroll
        for (int t = 0; t < GPT; ++t)
            sm[SO_V + ge_s[t]] = pf[t];
        __syncthreads();

        // ---- prefetch next iter (hidden behind GEMV + spline) -------------
        if (it + 1 < ITERS) {
            const float* base = &data[(size_t)(nbase + ROWS_IT) * NDIMT];
#pragma unroll
            for (int t = 0; t < GPT; ++t) pf[t] = __ldg(&base[ge_a[t]]);
        }

        // ---- fwd GEMV (i4 x r4, U in regs) + fused RQ spline ---------------
        {
            unsigned long long acc[4][2] = {{0,0},{0,0},{0,0},{0,0}};
#pragma unroll 6
            for (int j = 0; j < 48; ++j) {
                const float4 q = *(const float4*)&sm[SO_Q + j * 48 + i0];       // bcast
                const ulonglong2 v = *(const ulonglong2*)&sm[SO_V + j * RST + r0];
                const unsigned long long q0 = splat2(q.x), q1 = splat2(q.y);
                const unsigned long long q2 = splat2(q.z), q3 = splat2(q.w);
                ffma2(acc[0][0], q0, v.x); ffma2(acc[0][1], q0, v.y);
                ffma2(acc[1][0], q1, v.x); ffma2(acc[1][1], q1, v.y);
                ffma2(acc[2][0], q2, v.x); ffma2(acc[2][1], q2, v.y);
                ffma2(acc[3][0], q3, v.x); ffma2(acc[3][1], q3, v.y);
            }
            float pd[4] = {1.f, 1.f, 1.f, 1.f};   // product of d per r-lane
#pragma unroll
            for (int s = 0; s < 4; ++s) {
                const int i = i0 + s;
                const float*  xr = &sm[SO_X + i * MKNOT];
                const float2* yd = ydk + i * MKNOT;
                const unsigned char* lut = slut + i * 256;
                const float xlo = sm[SO_XLO + i];
                const float ivw = sm[SO_IVW + i];

                float2 ua = unpk2(acc[s][0]);
                float2 ub = unpk2(acc[s][1]);
                float u[4] = {ua.x, ua.y, ub.x, ub.y};
                float4 sv;
                float d0, d1, d2, d3;
                sv.x = rq_eval(u[0], xr, yd, lut, xlo, ivw, d0) - u[0];
                sv.y = rq_eval(u[1], xr, yd, lut, xlo, ivw, d1) - u[1];
                sv.z = rq_eval(u[2], xr, yd, lut, xlo, ivw, d2) - u[2];
                sv.w = rq_eval(u[3], xr, yd, lut, xlo, ivw, d3) - u[3];
                *(float4*)&sm[SO_S + i * RST + r0] = sv;
                pd[0] *= d0; pd[1] *= d1; pd[2] *= d2; pd[3] *= d3;
            }
            // one log per r-lane (log of product == sum of logs to fp32 rounding)
            float4 lj4;
            lj4.x = __logf(pd[0]); lj4.y = __logf(pd[1]);
            lj4.z = __logf(pd[2]); lj4.w = __logf(pd[3]);
            *(float4*)&sm[SO_LJ + ig * 256 + r0] = lj4;
        }
        __syncthreads();

        // ---- bwd GEMV: W[j][r] = sum_i QT[i][j]*S[i][r]; V += W in place ---
        {
            unsigned long long acc[4][2] = {{0,0},{0,0},{0,0},{0,0}};
            const int j0 = i0;
#pragma unroll 6
            for (int i = 0; i < 48; ++i) {
                const float4 q = *(const float4*)&sm[SO_QT + i * 48 + j0];      // bcast
                const ulonglong2 v = *(const ulonglong2*)&sm[SO_S + i * RST + r0];
                const unsigned long long q0 = splat2(q.x), q1 = splat2(q.y);
                const unsigned long long q2 = splat2(q.z), q3 = splat2(q.w);
                ffma2(acc[0][0], q0, v.x); ffma2(acc[0][1], q0, v.y);
                ffma2(acc[1][0], q1, v.x); ffma2(acc[1][1], q1, v.y);
                ffma2(acc[2][0], q2, v.x); ffma2(acc[2][1], q2, v.y);
                ffma2(acc[3][0], q3, v.x); ffma2(acc[3][1], q3, v.y);
            }
#pragma unroll
            for (int p = 0; p < 4; ++p) {
                float4* vp = (float4*)&sm[SO_V + (j0 + p) * RST + r0];
                float4 v = *vp;                                   // exclusive tile
                float2 wa = unpk2(acc[p][0]);
                float2 wb = unpk2(acc[p][1]);
                v.x += wa.x; v.y += wa.y; v.z += wb.x; v.w += wb.y;
                *vp = v;
            }
        }
        __syncthreads();

        // ---- scatter (V holds V+W) + per-row logdet partials ---------------
        {
            float* obase = &out[(size_t)nbase * NDIMT];
#pragma unroll
            for (int t = 0; t < GPT; ++t)
                obase[ge_a[t]] = sm[SO_V + ge_s[t]];
            if (tid < ROWS_IT) {
                float s = 0.f;
#pragma unroll
                for (int g = 0; g < 12; ++g) s += sm[SO_LJ + g * 256 + tid];
                g_lj[(size_t)k * NSAMP + nbase + tid] = s;
            }
        }
    }
}

// ---------------------------------------------------------------------------
// Kernel 4: parallel deterministic logdet reduction.
// ---------------------------------------------------------------------------
__global__ void reduce_lj(float* __restrict__ logj) {
    __shared__ float sb[256];
    const int t  = threadIdx.x;
    const int n  = blockIdx.x * 32 + (t >> 3);
    const int kc = t & 7;
    float s = 0.f;
#pragma unroll
    for (int u = 0; u < 8; ++u)
        s += __ldg(&g_lj[(size_t)(kc * 8 + u) * NSAMP + n]);
    sb[t] = s;
    __syncthreads();
    if (kc == 0) {
        float r = 0.f;
#pragma unroll
        for (int u = 0; u < 8; ++u) r += sb[t + u];   // fixed order
        logj[n] = r;
    }
}

// ---------------------------------------------------------------------------
// Launch
// ---------------------------------------------------------------------------
extern "C" void kernel_launch(void* const* d_in, const int* in_sizes, int n_in,
                              void* d_out, int out_size) {
    const float* data     = (const float*)d_in[0];
    const float* A_raw    = (const float*)d_in[1];
    const float* x0       = (const float*)d_in[2];
    const float* logdx    = (const float*)d_in[3];
    const float* y0       = (const float*)d_in[4];
    const float* logdy    = (const float*)d_in[5];
    const float* logderiv = (const float*)d_in[6];

    float* out  = (float*)d_out;
    float* logj = out + (size_t)NSAMP * NDIMT;

    cudaFuncSetAttribute(fused_kernel,
                         cudaFuncAttributeMaxDynamicSharedMemorySize, SMEM_BYTES);

    prep_kernel<<<ORTH_BLOCKS + KNOT_BLOCKS, PREP_TPB>>>(A_raw, x0, logdx,
                                                         y0, logdy, logderiv);
    fused_kernel<<<dim3(NKER, 16), TPB, SMEM_BYTES>>>(data, out);
    reduce_lj<<<NSAMP / 32, 256>>>(logj);
}